// round 10
// baseline (speedup 1.0000x reference)
#include <cuda_runtime.h>
#include <cstdint>

#define MAX_N 100000
#define IN_DIM 192
#define NEG_SLOPE 0.2f
#define EDGE_ILP 4
#define NODE_ILP 4

// Scratch (allocation-free rule: __device__ globals).
// g_rec[n]  = {xproj0, xproj1, a_src, a_dst}
// g_adst[n] = a_dst packed (dense -> better L1 behavior on gathers)
// g_acc[n]  = {sum e*xp0, sum e*xp1, sum e, pad}
__device__ float4 g_rec[MAX_N];
__device__ float  g_adst[MAX_N];
__device__ float4 g_acc[MAX_N];
__device__ int    g_is64;   // 1 if edge_index is int64, 0 if int32

// ---------------------------------------------------------------------------
// Kernel 1: projection + logits + self-loop init. Warp-per-node, FOUR nodes
// per warp-iteration: 12 front-batched LDG.64 (MLP=12), 8 independent FFMA
// chains, 8 independent shuffle-reduce chains. Block 0 warp 0 also runs the
// int64/int32 detector.
// ---------------------------------------------------------------------------
__global__ __launch_bounds__(256)
void gat_project_kernel(const float* __restrict__ x,
                        const float* __restrict__ W,        // [IN_DIM,2]
                        const float* __restrict__ att_src,  // [2]
                        const float* __restrict__ att_dst,  // [2]
                        const int* __restrict__ eidx_w,     // edge_index words
                        int det_nwords,                     // 0 => force is64=1
                        int N)
{
    if (blockIdx.x == 0 && threadIdx.x < 32) {
        int notz = 0;
        if (det_nwords > 0) {
            for (int i = threadIdx.x; i < 2048; i += 32) {
                int p = 2 * i + 1;                 // odd 32-bit words
                if (p < det_nwords && eidx_w[p] != 0) notz = 1;
            }
        }
        notz = __any_sync(0xffffffffu, notz);
        if (threadIdx.x == 0) g_is64 = (det_nwords > 0) ? (notz ? 0 : 1) : 1;
    }

    int lane  = threadIdx.x & 31;
    int warp  = (blockIdx.x * blockDim.x + threadIdx.x) >> 5;
    int nwarp = (gridDim.x * blockDim.x) >> 5;

    // W float4 q covers rows 2q,2q+1 -> {W[2q][0],W[2q][1],W[2q+1][0],W[2q+1][1]}
    const float4* W4 = (const float4*)W;
    float4 w0 = __ldg(W4 + lane);
    float4 w1 = __ldg(W4 + lane + 32);
    float4 w2 = __ldg(W4 + lane + 64);
    float as0 = __ldg(att_src + 0), as1 = __ldg(att_src + 1);
    float ad0 = __ldg(att_dst + 0), ad1 = __ldg(att_dst + 1);

    for (int n0 = NODE_ILP * warp; n0 < N; n0 += NODE_ILP * nwarp) {
        int nn[NODE_ILP];
        float2 v0[NODE_ILP], v1[NODE_ILP], v2[NODE_ILP];
#pragma unroll
        for (int j = 0; j < NODE_ILP; j++) {
            int n = n0 + j;
            nn[j] = (n < N) ? n : (N - 1);         // clamp (safe duplicate load)
            const float2* xr = (const float2*)(x + (size_t)nn[j] * IN_DIM);
            v0[j] = __ldg(xr + lane);
            v1[j] = __ldg(xr + lane + 32);
            v2[j] = __ldg(xr + lane + 64);
        }

        float p0[NODE_ILP], p1[NODE_ILP];
#pragma unroll
        for (int j = 0; j < NODE_ILP; j++) {
            p0[j] = v0[j].x * w0.x + v0[j].y * w0.z
                  + v1[j].x * w1.x + v1[j].y * w1.z
                  + v2[j].x * w2.x + v2[j].y * w2.z;
            p1[j] = v0[j].x * w0.y + v0[j].y * w0.w
                  + v1[j].x * w1.y + v1[j].y * w1.w
                  + v2[j].x * w2.y + v2[j].y * w2.w;
        }

#pragma unroll
        for (int off = 16; off > 0; off >>= 1) {   // 8 independent chains
#pragma unroll
            for (int j = 0; j < NODE_ILP; j++) {
                p0[j] += __shfl_xor_sync(0xffffffffu, p0[j], off);
                p1[j] += __shfl_xor_sync(0xffffffffu, p1[j], off);
            }
        }

        if (lane == 0) {
#pragma unroll
            for (int j = 0; j < NODE_ILP; j++) {
                int n = n0 + j;
                if (n < N) {
                    float a_s = p0[j] * as0 + p1[j] * as1;
                    float a_d = p0[j] * ad0 + p1[j] * ad1;
                    g_rec[n]  = make_float4(p0[j], p1[j], a_s, a_d);
                    g_adst[n] = a_d;
                    float alpha = a_s + a_d;       // self-loop edge
                    alpha = (alpha >= 0.f) ? alpha : NEG_SLOPE * alpha;
                    float ev = __expf(alpha);
                    g_acc[n] = make_float4(ev * p0[j], ev * p1[j], ev, 0.f);
                }
            }
        }
    }
}

// ---------------------------------------------------------------------------
// Kernel 2 (unchanged): single fused pass over edges, ILP=4.
//   alpha = leakyrelu(a_src[s] + a_dst[d]); e = exp(alpha)
//   acc[d] += {e*xp0[s], e*xp1[s], e, 0}  via one red.global.add.v4.f32
// (softmax max-subtraction elided: scale-invariant; fp32-safe here)
// ---------------------------------------------------------------------------
__global__ __launch_bounds__(256)
void gat_edge_kernel(const void* __restrict__ edge_index, int E, int N)
{
    int base = blockIdx.x * (256 * EDGE_ILP) + threadIdx.x;
    int is64 = g_is64;
    bool full = (blockIdx.x + 1) * (256 * EDGE_ILP) <= E;

    int s[EDGE_ILP], d[EDGE_ILP];
    if (full) {
#pragma unroll
        for (int i = 0; i < EDGE_ILP; i++) {
            int e = base + i * 256;
            if (is64) {
                const long long* ei = (const long long*)edge_index;
                s[i] = (int)__ldg(ei + e);
                d[i] = (int)__ldg(ei + E + e);
            } else {
                const int* ei = (const int*)edge_index;
                s[i] = __ldg(ei + e);
                d[i] = __ldg(ei + E + e);
            }
        }
    } else {
#pragma unroll
        for (int i = 0; i < EDGE_ILP; i++) {
            int e = base + i * 256;
            s[i] = -1; d[i] = -1;
            if (e < E) {
                if (is64) {
                    const long long* ei = (const long long*)edge_index;
                    s[i] = (int)__ldg(ei + e);
                    d[i] = (int)__ldg(ei + E + e);
                } else {
                    const int* ei = (const int*)edge_index;
                    s[i] = __ldg(ei + e);
                    d[i] = __ldg(ei + E + e);
                }
            }
        }
    }

    float4 rs[EDGE_ILP];
    float  ad[EDGE_ILP];
#pragma unroll
    for (int i = 0; i < EDGE_ILP; i++) {
        if ((unsigned)s[i] < (unsigned)N && (unsigned)d[i] < (unsigned)N) {
            rs[i] = __ldg(&g_rec[s[i]]);        // 16B gather
            ad[i] = __ldg(&g_adst[d[i]]);       // 4B gather, dense array
        }
    }

#pragma unroll
    for (int i = 0; i < EDGE_ILP; i++) {
        if ((unsigned)s[i] < (unsigned)N && (unsigned)d[i] < (unsigned)N) {
            float alpha = rs[i].z + ad[i];
            alpha = (alpha >= 0.f) ? alpha : NEG_SLOPE * alpha;
            float ev = __expf(alpha);
            float v0 = ev * rs[i].x;
            float v1 = ev * rs[i].y;
            asm volatile("red.global.add.v4.f32 [%0], {%1, %2, %3, %4};"
                         :: "l"(&g_acc[d[i]]), "f"(v0), "f"(v1), "f"(ev), "f"(0.f)
                         : "memory");
        }
    }
}

// ---------------------------------------------------------------------------
// Kernel 3: normalize + bias. 2 nodes/thread, packed float4 store.
// ---------------------------------------------------------------------------
__global__ __launch_bounds__(256)
void gat_final_kernel(float* __restrict__ out,
                      const float* __restrict__ bias,
                      int N)
{
    int i = blockIdx.x * blockDim.x + threadIdx.x;   // pair index
    int n0 = 2 * i;
    if (n0 >= N) return;
    float b0 = __ldg(bias + 0), b1 = __ldg(bias + 1);

    float4 a0 = g_acc[n0];
    float inv0 = 1.0f / (a0.z + 1e-16f);
    if (n0 + 1 < N) {
        float4 a1 = g_acc[n0 + 1];
        float inv1 = 1.0f / (a1.z + 1e-16f);
        float4 o = make_float4(a0.x * inv0 + b0, a0.y * inv0 + b1,
                               a1.x * inv1 + b0, a1.y * inv1 + b1);
        ((float4*)out)[i] = o;
    } else {
        ((float2*)out)[n0] = make_float2(a0.x * inv0 + b0, a0.y * inv0 + b1);
    }
}

// ---------------------------------------------------------------------------
// Input identification by element count (robust to metadata ordering):
//   x = largest; edge_index = 2nd; edge_attr = 3rd (gives E); W = 384;
//   att_src, att_dst, bias = the three size-2 tensors in appearance order.
// ---------------------------------------------------------------------------
extern "C" void kernel_launch(void* const* d_in, const int* in_sizes, int n_in,
                              void* d_out, int out_size)
{
    int i_x = -1, i_eidx = -1, i_attr = -1, i_W = -1;
    int small[3] = {-1, -1, -1};
    int nsmall = 0;
    {
        long long best = -1;
        for (int i = 0; i < n_in; i++)
            if (in_sizes[i] > best) { best = in_sizes[i]; i_x = i; }
        best = -1;
        for (int i = 0; i < n_in; i++)
            if (i != i_x && in_sizes[i] > best) { best = in_sizes[i]; i_eidx = i; }
        best = -1;
        for (int i = 0; i < n_in; i++)
            if (i != i_x && i != i_eidx && in_sizes[i] > best) { best = in_sizes[i]; i_attr = i; }
    }
    for (int i = 0; i < n_in; i++) {
        if (i == i_x || i == i_eidx || i == i_attr) continue;
        if (in_sizes[i] > 16) { i_W = i; }
        else if (nsmall < 3) { small[nsmall++] = i; }
    }

    const float* x       = (const float*)d_in[i_x];
    const void*  eidx    = d_in[i_eidx];
    const float* W       = (const float*)d_in[i_W];
    const float* att_src = (const float*)d_in[small[0]];
    const float* att_dst = (const float*)d_in[small[1]];
    const float* bias    = (const float*)d_in[small[2]];
    float* out           = (float*)d_out;

    int N = in_sizes[i_x] / IN_DIM;
    int E = in_sizes[i_attr];               // edge_attr is [E,1]
    int eidx_elems = in_sizes[i_eidx];

    // dtype: ratio 4 => int64 reported as word count (det_nwords=0 => force 64).
    // ratio 2 => ambiguous; K1 block 0 samples odd words on device.
    int det_nwords = (eidx_elems == 4 * E) ? 0 : (2 * E);

    // K1: persistent warp loop, 4 nodes per warp-iteration
    gat_project_kernel<<<1184, 256>>>(x, W, att_src, att_dst,
                                      (const int*)eidx, det_nwords, N);

    // K2: ILP=4 edges per thread, full grid
    int blocks2 = (E + 256 * EDGE_ILP - 1) / (256 * EDGE_ILP);
    gat_edge_kernel<<<blocks2, 256>>>(eidx, E, N);

    // K3: normalize + bias, 2 nodes/thread
    int pairs = (N + 1) / 2;
    gat_final_kernel<<<(pairs + 255) / 256, 256>>>(out, bias, N);
}